// round 1
// baseline (speedup 1.0000x reference)
#include <cuda_runtime.h>
#include <math.h>

#define NPTS 4096
#define BITD 64
#define LLAB 10
#define RT   256
#define UPPERB 16.0f
// c = (1/right)*ln(yp/(99(1-yp))) with right=64/6, yp=0.5  -> -6*ln(99)/64
#define CONST_C    (-0.43079248594386178f)
#define CONST_AC   (-0.86158497188772356f)   // a*c, a = 2 exactly
#define CONST_BASE (0.0f)

// ---------------- device scratch (no allocations allowed) ----------------
__device__ float    g_inner[(size_t)NPTS * NPTS];   // 64 MB
__device__ unsigned g_maskArr[NPTS];
__device__ float    g_rowres[NPTS];
__device__ float    g_rowvalid[NPTS];

// ---------------- helpers ----------------
__device__ __forceinline__ unsigned fkey(float f) {
    unsigned u = __float_as_uint(f);
    return u ^ ((u >> 31) ? 0xFFFFFFFFu : 0x80000000u);  // monotonic float->uint
}
__device__ __forceinline__ float finv(unsigned k) {
    unsigned u = (k & 0x80000000u) ? (k ^ 0x80000000u) : ~k;
    return __uint_as_float(u);
}
__device__ __forceinline__ float softplusf(float x) {
    return fmaxf(x, 0.f) + log1pf(__expf(-fabsf(x)));
}

__device__ __forceinline__ float blockReduceF(float v, float* sh) {
    int tid = threadIdx.x, lane = tid & 31, wid = tid >> 5;
    #pragma unroll
    for (int o = 16; o > 0; o >>= 1) v += __shfl_down_sync(0xffffffffu, v, o);
    if (lane == 0) sh[wid] = v;
    __syncthreads();
    if (tid == 0) {
        float s = 0.f;
        #pragma unroll
        for (int w = 0; w < RT / 32; w++) s += sh[w];
        sh[0] = s;
    }
    __syncthreads();
    v = sh[0];
    __syncthreads();
    return v;
}
__device__ __forceinline__ int blockReduceI(int v, int* sh) {
    int tid = threadIdx.x, lane = tid & 31, wid = tid >> 5;
    #pragma unroll
    for (int o = 16; o > 0; o >>= 1) v += __shfl_down_sync(0xffffffffu, v, o);
    if (lane == 0) sh[wid] = v;
    __syncthreads();
    if (tid == 0) {
        int s = 0;
        #pragma unroll
        for (int w = 0; w < RT / 32; w++) s += sh[w];
        sh[0] = s;
    }
    __syncthreads();
    v = sh[0];
    __syncthreads();
    return v;
}

// ---------------- kernel 0: label bitmasks ----------------
__global__ void mask_kernel(const int* __restrict__ y) {
    int i = blockIdx.x * blockDim.x + threadIdx.x;
    if (i < NPTS) {
        unsigned m = 0;
        #pragma unroll
        for (int l = 0; l < LLAB; l++) m |= (y[i * LLAB + l] != 0 ? 1u : 0u) << l;
        g_maskArr[i] = m;
    }
}

// ---------------- kernel 1: inner = U @ V^T ----------------
// 128x128 tile, 256 threads, 8x8 micro-tile, K staged in halves of 32.
#define TK   32
#define TPAD 36   // 32 + 4 pad; keeps float4 alignment, <=2-way LDS conflicts
__global__ void __launch_bounds__(256) gemm_kernel(const float* __restrict__ U,
                                                   const float* __restrict__ V) {
    __shared__ float As[128][TPAD];
    __shared__ float Bs[128][TPAD];
    int tid = threadIdx.x;
    int tx = tid & 15, ty = tid >> 4;       // 16 x 16 thread grid
    int brow = blockIdx.y * 128, bcol = blockIdx.x * 128;
    int lr = tid >> 3;                      // 0..31 (rows per load iter)
    int lc4 = tid & 7;                      // 0..7  (float4 within k-half)

    float acc[8][8];
    #pragma unroll
    for (int i = 0; i < 8; i++)
        #pragma unroll
        for (int j = 0; j < 8; j++) acc[i][j] = 0.f;

    for (int ks = 0; ks < BITD; ks += TK) {
        #pragma unroll
        for (int it = 0; it < 4; it++) {
            int r = it * 32 + lr;
            float4 a = *(const float4*)(U + (size_t)(brow + r) * BITD + ks + lc4 * 4);
            *(float4*)(&As[r][lc4 * 4]) = a;
            float4 b = *(const float4*)(V + (size_t)(bcol + r) * BITD + ks + lc4 * 4);
            *(float4*)(&Bs[r][lc4 * 4]) = b;
        }
        __syncthreads();
        #pragma unroll 4
        for (int k = 0; k < TK; k++) {
            float ar[8], bc[8];
            #pragma unroll
            for (int x = 0; x < 8; x++) ar[x] = As[ty * 8 + x][k];
            #pragma unroll
            for (int x = 0; x < 8; x++) bc[x] = Bs[tx + 16 * x][k];
            #pragma unroll
            for (int i = 0; i < 8; i++)
                #pragma unroll
                for (int j = 0; j < 8; j++) acc[i][j] = fmaf(ar[i], bc[j], acc[i][j]);
        }
        __syncthreads();
    }
    #pragma unroll
    for (int i = 0; i < 8; i++) {
        int row = brow + ty * 8 + i;
        #pragma unroll
        for (int j = 0; j < 8; j++)
            g_inner[(size_t)row * NPTS + bcol + tx + 16 * j] = acc[i][j];
    }
}

// ---------------- radix select: sum of q smallest (by flipped key) ----------------
// flip = 0        -> q smallest values
// flip = ~0       -> q largest values
// Exact tie handling: sum(strictly below T) + (q - countBelow) * value(T).
__device__ float radixSelSum(const float* vals, int lo, int hi, int q, unsigned flip,
                             unsigned* hist, float* fsh, int* ish,
                             unsigned* wsh, unsigned* bres) {
    int tid = threadIdx.x, lane = tid & 31, wid = tid >> 5;
    if (q <= 0) return 0.f;
    int n = hi - lo;
    if (q >= n) {
        float s = 0.f;
        for (int idx = lo + tid; idx < hi; idx += RT) s += vals[idx];
        return blockReduceF(s, fsh);
    }
    unsigned prefix = 0;
    unsigned qq = (unsigned)q;
    for (int pass = 3; pass >= 0; pass--) {
        int shift = pass * 8;
        unsigned hiMask = (pass == 3) ? 0u : (0xFFFFFFFFu << (shift + 8));
        hist[tid] = 0u;
        __syncthreads();
        for (int idx = lo + tid; idx < hi; idx += RT) {
            unsigned k = fkey(vals[idx]) ^ flip;
            if ((k & hiMask) == prefix) atomicAdd(&hist[(k >> shift) & 255u], 1u);
        }
        __syncthreads();
        unsigned h = hist[tid];
        unsigned v = h;
        #pragma unroll
        for (int o = 1; o < 32; o <<= 1) {
            unsigned t = __shfl_up_sync(0xffffffffu, v, o);
            if (lane >= o) v += t;
        }
        if (lane == 31) wsh[wid] = v;
        __syncthreads();
        unsigned wbase = 0;
        #pragma unroll
        for (int w = 0; w < 8; w++) if (w < wid) wbase += wsh[w];
        unsigned incl = wbase + v;
        unsigned excl = incl - h;
        if (excl < qq && qq <= incl) { bres[0] = (unsigned)tid; bres[1] = qq - excl; }
        __syncthreads();
        prefix |= bres[0] << shift;
        qq = bres[1];
        __syncthreads();
    }
    float sLess = 0.f; int cLess = 0;
    for (int idx = lo + tid; idx < hi; idx += RT) {
        float vv = vals[idx];
        unsigned k = fkey(vv) ^ flip;
        if (k < prefix) { sLess += vv; cLess++; }
    }
    sLess = blockReduceF(sLess, fsh);
    cLess = blockReduceI(cLess, ish);
    float tVal = finv(prefix ^ flip);
    return sLess + (float)(q - cLess) * tVal;
}

// ---------------- kernel 2: per-row loss ----------------
__global__ void __launch_bounds__(RT) row_kernel() {
    __shared__ float    vals[NPTS];      // similar compacted to front, dissimilar to back
    __shared__ unsigned hist[256];
    __shared__ float    fsh[RT / 32];
    __shared__ int      ish[RT / 32];
    __shared__ unsigned wsh[RT / 32];
    __shared__ unsigned wcS[RT / 32];
    __shared__ unsigned bres[2];

    int tid = threadIdx.x, lane = tid & 31, wid = tid >> 5;
    int i = blockIdx.x;
    unsigned mi = g_maskArr[i];
    const float* __restrict__ row = g_inner + (size_t)i * NPTS;

    // deterministic compaction + class sums
    float sS = 0.f, sD = 0.f;
    int baseS = 0;
    for (int it = 0; it < NPTS / RT; it++) {
        int j = it * RT + tid;
        float x = row[j];
        bool sim = (mi & g_maskArr[j]) != 0u;
        unsigned bal = __ballot_sync(0xffffffffu, sim);
        int nS = __popc(bal);
        if (lane == 0) wcS[wid] = (unsigned)nS;
        __syncthreads();
        int wb = baseS, tot = 0;
        #pragma unroll
        for (int w = 0; w < RT / 32; w++) {
            int cw = (int)wcS[w];
            tot += cw;
            if (w < wid) wb += cw;
        }
        unsigned below = bal & ((1u << lane) - 1u);
        int simBefore = wb + __popc(below);
        if (sim) {
            vals[simBefore] = x; sS += x;
        } else {
            int g = it * RT + wid * 32 + lane;      // global j order index
            int dpos = g - simBefore;               // dissimilars before this one
            vals[NPTS - 1 - dpos] = x; sD += x;
        }
        __syncthreads();
        baseS += tot;
    }
    int ns = baseS;
    int nd = NPTS - ns;

    sS = blockReduceF(sS, fsh);
    sD = blockReduceF(sD, fsh);

    int ks = (ns * 9) / 10, kd = (nd * 9) / 10;
    int qs = ns - ks, qd = nd - kd;

    float simMinSum = radixSelSum(vals, 0, ns, qs, 0u, hist, fsh, ish, wsh, bres);
    float disMaxSum = radixSelSum(vals, ns, NPTS, qd, 0xFFFFFFFFu, hist, fsh, ish, wsh, bres);

    float similarMin    = simMinSum / (float)max(qs, 1);
    float dissimilarMax = disMaxSum / (float)max(qd, 1);
    float meanS  = fminf(fmaxf(sS / (float)max(ns, 1), 0.f), UPPERB);
    float meanDS = fminf(fmaxf(sD / (float)max(nd, 1), 0.f), UPPERB);

    float BP   = meanS  - (UPPERB - meanS) / UPPERB * fabsf(meanS - dissimilarMax);
    float BPds = meanDS - meanDS / UPPERB * fabsf(meanDS - similarMin);

    float dcf = CONST_BASE - CONST_C  * BP;
    float gcf = CONST_BASE - CONST_AC * BP;
    float d2  = CONST_BASE - CONST_C  * BPds;
    float g2  = CONST_BASE - CONST_AC * BPds;

    float pos = 0.f, nav = 0.f;
    for (int it = 0; it < NPTS / RT; it++) {
        int idx = it * RT + tid;
        float x = vals[idx];
        if (idx < ns) {
            float f = (x > BP) ? fmaf(CONST_C, x, dcf) : fmaf(CONST_AC, x, gcf);
            pos += softplusf(f);
        } else {
            float f = (x < BPds) ? fmaf(CONST_C, x, d2) : fmaf(CONST_AC, x, g2);
            nav += softplusf(-f);
        }
    }
    pos = blockReduceF(pos, fsh);
    nav = blockReduceF(nav, fsh);

    if (tid == 0) {
        bool valid = (ns > 0) && (nd > 0);
        float r = pos / (float)max(ns, 1) + nav / (float)max(nd, 1);
        g_rowres[i]   = valid ? r : 0.f;
        g_rowvalid[i] = valid ? 1.f : 0.f;
    }
}

// ---------------- kernel 3: finalize ----------------
__global__ void __launch_bounds__(RT) finalize_kernel(float* __restrict__ out) {
    __shared__ float fsh[RT / 32];
    int tid = threadIdx.x;
    float t = 0.f, c = 0.f;
    for (int idx = tid; idx < NPTS; idx += RT) {
        t += g_rowres[idx];
        c += g_rowvalid[idx];
    }
    t = blockReduceF(t, fsh);
    c = blockReduceF(c, fsh);
    if (tid == 0) out[0] = (c > 0.f) ? t / fmaxf(c, 1.f) : 0.f;
}

// ---------------- launch ----------------
extern "C" void kernel_launch(void* const* d_in, const int* in_sizes, int n_in,
                              void* d_out, int out_size) {
    const float* u = (const float*)d_in[0];
    const float* v = (const float*)d_in[1];
    const int*   y = (const int*)d_in[2];

    mask_kernel<<<(NPTS + 255) / 256, 256>>>(y);
    dim3 gg(NPTS / 128, NPTS / 128);
    gemm_kernel<<<gg, 256>>>(u, v);
    row_kernel<<<NPTS, RT>>>();
    finalize_kernel<<<1, RT>>>((float*)d_out);
}